// round 2
// baseline (speedup 1.0000x reference)
#include <cuda_runtime.h>

#define SQ  256
#define NH  16
#define HD  64
#define HIDW 1024

static __device__ float  g_Q[NH*SQ*HD];
static __device__ float  g_K[NH*SQ*HD];
static __device__ float  g_V[NH*SQ*HD];
static __device__ float  g_S[NH*SQ*SQ];
static __device__ float  g_P[NH*SQ*SQ];
static __device__ float2 g_AP[NH*SQ*SQ];
static __device__ float  g_P2[NH*SQ];
static __device__ float  g_Ctx[SQ*HIDW];
static __device__ float  g_Part[NH*64*4*HD];   // [h][x(64)][r(4)][d]

__device__ __forceinline__ float ex2f(float x){ float y; asm("ex2.approx.ftz.f32 %0, %1;" : "=f"(y) : "f"(x)); return y; }
__device__ __forceinline__ float rcpf(float x){ float y; asm("rcp.approx.ftz.f32 %0, %1;" : "=f"(y) : "f"(x)); return y; }

#define LOG2E 1.4426950408889634f

// ---------------------------------------------------------------------------
// Generic fp32 tiled GEMM with mode-specific epilogues.
// MODE 0: fused = hidden @ W_qkv + b_qkv, scattered into Q/K/V head-major
// MODE 1: S[h] = Q[h] @ K[h]^T            (TRANSB, per-head batch via z)
// MODE 2: Ctx[:, h*64: ] = P[h] @ V[h]
// MODE 3: out = Ctx @ W_dense + b_dense + residual
// ---------------------------------------------------------------------------
template<int BM,int BN,int BK,int TM,int TN,bool TRANSB,int MODE>
__global__ void gemm_k(const float* __restrict__ inA, const float* __restrict__ inB,
                       const float* __restrict__ bias, const float* __restrict__ resid,
                       float* __restrict__ outp)
{
    constexpr int LDA = (MODE==0)?HIDW  :(MODE==1)?HD:(MODE==2)?SQ:HIDW;
    constexpr int LDB = (MODE==0)?3*HIDW:(MODE==1)?HD:(MODE==2)?HD:HIDW;
    constexpr int KT  = (MODE==0)?HIDW  :(MODE==1)?HD:(MODE==2)?SQ:HIDW;

    __shared__ float As[BK][BM+4];
    __shared__ float Bs[BK][BN+4];

    const int tid = threadIdx.x;
    const int tx  = tid % (BN/TN);
    const int ty  = tid / (BN/TN);
    const int n0  = blockIdx.x * BN;
    const int m0  = blockIdx.y * BM;
    const int z   = blockIdx.z;

    const float* A;
    const float* B;
    if      (MODE==0) { A = inA;            B = inB; }
    else if (MODE==1) { A = g_Q + z*SQ*HD;  B = g_K + z*SQ*HD; }
    else if (MODE==2) { A = g_P + z*SQ*SQ;  B = g_V + z*SQ*HD; }
    else              { A = g_Ctx;          B = inB; }

    float acc[TM][TN];
#pragma unroll
    for (int r=0;r<TM;r++)
#pragma unroll
        for (int c=0;c<TN;c++) acc[r][c]=0.f;

    for (int k0=0;k0<KT;k0+=BK) {
#pragma unroll
        for (int x=tid; x<BM*BK; x+=256) {
            int m = x / BK, kk = x % BK;
            As[kk][m] = A[(m0+m)*LDA + k0+kk];
        }
        if constexpr (!TRANSB) {
#pragma unroll
            for (int x=tid; x<BK*BN; x+=256) {
                int kk = x / BN, n = x % BN;
                Bs[kk][n] = B[(k0+kk)*LDB + n0+n];
            }
        } else {
#pragma unroll
            for (int x=tid; x<BN*BK; x+=256) {
                int n = x / BK, kk = x % BK;
                Bs[kk][n] = B[(n0+n)*LDB + k0+kk];
            }
        }
        __syncthreads();
#pragma unroll
        for (int k=0;k<BK;k++){
            float a[TM], b[TN];
            if constexpr (TM==4) {
                float4 t = *reinterpret_cast<const float4*>(&As[k][ty*TM]);
                a[0]=t.x; a[1]=t.y; a[2]=t.z; a[3]=t.w;
            } else {
                float2 t = *reinterpret_cast<const float2*>(&As[k][ty*TM]);
                a[0]=t.x; a[1]=t.y;
            }
            {
                float4 t = *reinterpret_cast<const float4*>(&Bs[k][tx*TN]);
                b[0]=t.x; b[1]=t.y; b[2]=t.z; b[3]=t.w;
            }
#pragma unroll
            for (int r=0;r<TM;r++)
#pragma unroll
                for (int c=0;c<TN;c++)
                    acc[r][c] = fmaf(a[r], b[c], acc[r][c]);
        }
        __syncthreads();
    }

#pragma unroll
    for (int r=0;r<TM;r++){
        int m = m0 + ty*TM + r;
#pragma unroll
        for (int c=0;c<TN;c++){
            int n = n0 + tx*TN + c;
            float v = acc[r][c];
            if constexpr (MODE==0) {
                v += bias[n];
                int hh    = n / (3*HD);
                int rem   = n - hh*(3*HD);
                int which = rem / HD;
                int dd    = rem - which*HD;
                int idx   = (hh*SQ + m)*HD + dd;
                if (which==0)      g_Q[idx] = v;
                else if (which==1) g_K[idx] = v;
                else               g_V[idx] = v;
            } else if constexpr (MODE==1) {
                g_S[(z*SQ + m)*SQ + n] = v;
            } else if constexpr (MODE==2) {
                g_Ctx[m*HIDW + z*HD + n] = v;
            } else {
                outp[m*HIDW + n] = v + bias[n] + resid[m*HIDW + n];
            }
        }
    }
}

// ---------------------------------------------------------------------------
// Per-row softmax: p = softmax(alibi + 0.125*S + mask), plus
// A_j = exp(S/64) (0 for masked j) and P2 = sum_j p^2.  One block per (h,i).
// ---------------------------------------------------------------------------
__global__ void softmax_k(const float* __restrict__ alibi, const float* __restrict__ mask)
{
    __shared__ float red[8];
    const int row = blockIdx.x;           // h*SQ + i
    const int h = row >> 8, i = row & 255;
    const int j = threadIdx.x;

    float s  = g_S[row*SQ + j];
    float sc = fmaf(0.125f, s, alibi[h*SQ + j]) + mask[i*SQ + j];

    float m = sc;
#pragma unroll
    for (int o=16;o;o>>=1) m = fmaxf(m, __shfl_xor_sync(0xffffffffu, m, o));
    if ((j&31)==0) red[j>>5] = m;
    __syncthreads();
    float bm = red[0];
#pragma unroll
    for (int t=1;t<8;t++) bm = fmaxf(bm, red[t]);
    float e = ex2f((sc - bm)*LOG2E);
    __syncthreads();

    float su = e;
#pragma unroll
    for (int o=16;o;o>>=1) su += __shfl_xor_sync(0xffffffffu, su, o);
    if ((j&31)==0) red[j>>5] = su;
    __syncthreads();
    float tot = red[0];
#pragma unroll
    for (int t=1;t<8;t++) tot += red[t];

    float p = e * rcpf(tot);
    g_P[row*SQ + j] = p;
    float a = (j<=i) ? ex2f(s * (LOG2E/64.f)) : 0.f;
    g_AP[row*SQ + j] = make_float2(a, p);

    float pq = p*p;
    __syncthreads();
#pragma unroll
    for (int o=16;o;o>>=1) pq += __shfl_xor_sync(0xffffffffu, pq, o);
    if ((j&31)==0) red[j>>5] = pq;
    __syncthreads();
    if (j==0){
        float t2 = red[0];
#pragma unroll
        for (int t=1;t<8;t++) t2 += red[t];
        g_P2[row] = t2;
    }
}

// ---------------------------------------------------------------------------
// qk_importance: single-pass per (h,i,d):
//   w_j = A_j * exp2(-q_d * k_jd * log2e/64)  for j<=i
//   contrib = (Σw²)/Z² − 2(Σw·p)/Z + Σp²
// Each lane owns one d for one row; no intra-warp reduction, no atomics.
// Block handles rows {x, x+64, x+128, x+192} of head h (balanced causal work).
// ---------------------------------------------------------------------------
__global__ void importance_k()
{
    const int tid  = threadIdx.x;
    const int w    = tid >> 5, lane = tid & 31;
    const int h    = blockIdx.y;
    const int r    = w >> 1;
    const int i    = blockIdx.x + 64*r;
    const int d    = ((w & 1) << 5) | lane;
    const int row  = h*SQ + i;

    const float qe = g_Q[row*HD + d] * (-LOG2E/64.f);
    const float*  kp = g_K + h*SQ*HD + d;    // stride HD per j, coalesced over lanes
    const float2* ap = g_AP + row*SQ;        // broadcast over lanes

    float Z=0.f, W2=0.f, WP=0.f;
#pragma unroll 4
    for (int j=0; j<=i; ++j) {
        float kv = kp[j*HD];
        float2 a = ap[j];
        float wv = a.x * ex2f(qe*kv);
        Z  += wv;
        W2  = fmaf(wv, wv,  W2);
        WP  = fmaf(wv, a.y, WP);
    }
    float iz = rcpf(Z);
    float contrib = fmaf(W2*iz, iz, -2.f*WP*iz) + g_P2[row];
    g_Part[((h*64 + blockIdx.x)*4 + r)*HD + d] = contrib;
}

__global__ void reduce_imp(float* __restrict__ imp)
{
    const int o = blockIdx.x*256 + threadIdx.x;   // 0..1023 = h*64+d
    const int h = o >> 6, d = o & 63;
    float s = 0.f;
#pragma unroll 8
    for (int t=0; t<256; ++t) s += g_Part[(h*256 + t)*HD + d];
    imp[o] = s;
}

// ---------------------------------------------------------------------------
extern "C" void kernel_launch(void* const* d_in, const int* in_sizes, int n_in,
                              void* d_out, int out_size)
{
    (void)in_sizes; (void)n_in; (void)out_size;
    const float* hidden   = (const float*)d_in[0];
    const float* residual = (const float*)d_in[1];
    const float* alibi    = (const float*)d_in[2];
    const float* amask    = (const float*)d_in[3];
    const float* Wqkv     = (const float*)d_in[4];
    const float* bqkv     = (const float*)d_in[5];
    const float* Wd       = (const float*)d_in[6];
    const float* bd       = (const float*)d_in[7];
    float* out = (float*)d_out;

    // 1. QKV projection + scatter
    gemm_k<64,64,16,4,4,false,0><<<dim3(48,4,1), 256>>>(hidden, Wqkv, bqkv, nullptr, nullptr);
    // 2. per-head scores S = Q K^T
    gemm_k<64,64,16,4,4,true, 1><<<dim3(4,4,16), 256>>>(nullptr, nullptr, nullptr, nullptr, nullptr);
    // 3. softmax p, A, P2
    softmax_k<<<4096, 256>>>(alibi, amask);
    // 4. qk importance partials + deterministic reduce
    importance_k<<<dim3(64,16,1), 256>>>();
    reduce_imp<<<4, 256>>>(out + SQ*HIDW);
    // 5. context = P V
    gemm_k<32,64,16,2,4,false,2><<<dim3(1,8,16), 256>>>(nullptr, nullptr, nullptr, nullptr, nullptr);
    // 6. dense projection + bias + residual
    gemm_k<32,64,16,2,4,false,3><<<dim3(16,8,1), 256>>>(nullptr, Wd, bd, residual, out);
}

// round 6
// speedup vs baseline: 1.6198x; 1.6198x over previous
#include <cuda_runtime.h>
#include <cstdint>

#define SQ   256
#define NH   16
#define HD   64
#define HIDW 1024
#define LOG2E 1.4426950408889634f

static __device__ float  g_Q[NH*SQ*HD];
static __device__ float  g_K[NH*SQ*HD];
static __device__ float  g_V[NH*SQ*HD];
static __device__ float  g_S[NH*SQ*SQ];
static __device__ float  g_P[NH*SQ*SQ];
static __device__ float2 g_AP[NH*SQ*SQ];
static __device__ float  g_P2[NH*SQ];
static __device__ float  g_Ctx[SQ*HIDW];
static __device__ float  g_Part[NH*SQ*HD];     // [row][d]
static __device__ float  g_Part2[4*NH*HD];     // [chunk][h*64+d]

__device__ __forceinline__ float ex2f(float x){ float y; asm("ex2.approx.ftz.f32 %0, %1;" : "=f"(y) : "f"(x)); return y; }
__device__ __forceinline__ float rcpf(float x){ float y; asm("rcp.approx.ftz.f32 %0, %1;" : "=f"(y) : "f"(x)); return y; }
__device__ __forceinline__ uint32_t f2tf32(float x){ uint32_t r; asm("cvt.rna.tf32.f32 %0, %1;" : "=r"(r) : "f"(x)); return r; }

__device__ __forceinline__ void mma8(float* c, const uint32_t* a, const uint32_t* b){
    asm volatile("mma.sync.aligned.m16n8k8.row.col.f32.tf32.tf32.f32 "
        "{%0,%1,%2,%3}, {%4,%5,%6,%7}, {%8,%9}, {%0,%1,%2,%3};"
        : "+f"(c[0]), "+f"(c[1]), "+f"(c[2]), "+f"(c[3])
        : "r"(a[0]), "r"(a[1]), "r"(a[2]), "r"(a[3]), "r"(b[0]), "r"(b[1]));
}

// ---------------------------------------------------------------------------
// tf32-split GEMM: D[128 x 64] = A[128 x KT] * B(k-major)[KT x 64]
// 3-term split (hi*hi + hi*lo + lo*hi) => fp32-grade accuracy on tensor cores.
// MODE 0: fused = hidden @ Wqkv (+bias) -> scatter Q/K/V   [B = Wqkv, direct]
// MODE 1: S[h]  = Q[h] @ K[h]^T                            [B = K, transposed at staging]
// MODE 2: Ctx   = P[h] @ V[h]                              [B = V, direct]
// MODE 3: out   = Ctx @ Wd (+bias+residual)                [B = Wd, direct]
// smem layouts (XOR-swizzled, conflict-free):
//   A: [k][m] stride 136, idx = k*136 + (m ^ (((k>>2)&3)<<3))
//   B: [k][n] stride  72, idx = k*72  + (n ^ (((k>>2)&3)<<3))
// ---------------------------------------------------------------------------
#define ASZ (32*136)
#define BSZ (32*72)
#define SMEM_BYTES ((2*ASZ + 2*BSZ)*4)

template<int MODE>
__global__ void __launch_bounds__(256, 1) mma_gemm(const float* __restrict__ Aext,
                                                   const float* __restrict__ Bext,
                                                   const float* __restrict__ bias,
                                                   const float* __restrict__ resid,
                                                   float* __restrict__ outp)
{
    constexpr int KT  = (MODE==1) ? 64 : (MODE==2) ? 256 : 1024;
    constexpr int NK  = KT/32;
    constexpr int LDA = (MODE==1) ? 64 : (MODE==2) ? 256 : 1024;
    constexpr int LDB = (MODE==0) ? 3072 : (MODE==1) ? 64 : (MODE==2) ? 64 : 1024;

    extern __shared__ float sm[];
    float* Ah = sm;
    float* Al = sm + ASZ;
    float* Bh = sm + 2*ASZ;
    float* Bl = sm + 2*ASZ + BSZ;
    const uint32_t* Ahu = (const uint32_t*)Ah;
    const uint32_t* Alu = (const uint32_t*)Al;
    const uint32_t* Bhu = (const uint32_t*)Bh;
    const uint32_t* Blu = (const uint32_t*)Bl;

    const int tid = threadIdx.x, lane = tid & 31, wid = tid >> 5;
    const int wm = wid >> 1, wn = wid & 1;
    const int tig = lane & 3, gid = lane >> 2;
    const int n0 = blockIdx.x*64, m0 = blockIdx.y*128, z = blockIdx.z;

    const float* Ag; const float* Bg;
    if constexpr (MODE==0)      { Ag = Aext;                      Bg = Bext; }
    else if constexpr (MODE==1) { Ag = g_Q + z*SQ*HD;             Bg = g_K + z*SQ*HD; }
    else if constexpr (MODE==2) { Ag = g_P + (size_t)z*SQ*SQ;     Bg = g_V + z*SQ*HD; }
    else                        { Ag = g_Ctx;                     Bg = Bext; }

    // staging maps
    const int kqw = tid & 3, mrw = (tid >> 2) & 7, aw = tid >> 5;   // A
    float4 pa[4]; float4 pb[2]; float pbt[8];

    auto loadA = [&](int kt){
#pragma unroll
        for (int mi = 0; mi < 2; mi++)
#pragma unroll
            for (int ki = 0; ki < 2; ki++) {
                int m = aw*8 + mrw + 64*mi, kq = kqw + 4*ki;
                pa[mi*2+ki] = *(const float4*)(Ag + (size_t)(m0+m)*LDA + kt*32 + kq*4);
            }
    };
    auto loadB = [&](int kt){
        if constexpr (MODE==1) {
            int d = tid & 31, jb = (tid >> 5) * 8;
#pragma unroll
            for (int r = 0; r < 8; r++)
                pbt[r] = Bg[(size_t)(n0 + jb + r)*LDB + kt*32 + d];
        } else {
#pragma unroll
            for (int r = 0; r < 2; r++) {
                int idx = tid + 256*r, kr = idx >> 4, nq = idx & 15;
                pb[r] = *(const float4*)(Bg + (size_t)(kt*32 + kr)*LDB + n0 + nq*4);
            }
        }
    };
    auto stage = [&](){
#pragma unroll
        for (int mi = 0; mi < 2; mi++)
#pragma unroll
            for (int ki = 0; ki < 2; ki++) {
                int m = aw*8 + mrw + 64*mi, kq = kqw + 4*ki;
                int mb = m ^ ((kq & 3) << 3);
                float4 v = pa[mi*2+ki];
                float vv[4] = {v.x, v.y, v.z, v.w};
#pragma unroll
                for (int e = 0; e < 4; e++) {
                    uint32_t hb = f2tf32(vv[e]);
                    float hf = __uint_as_float(hb);
                    uint32_t lb = f2tf32(vv[e] - hf);
                    Ah[(kq*4+e)*136 + mb] = hf;
                    Al[(kq*4+e)*136 + mb] = __uint_as_float(lb);
                }
            }
        if constexpr (MODE==1) {
            int d = tid & 31, jb = (tid >> 5) * 8;
            int C = ((d >> 2) & 3) << 3;
#pragma unroll
            for (int r = 0; r < 8; r++) {
                uint32_t hb = f2tf32(pbt[r]);
                float hf = __uint_as_float(hb);
                uint32_t lb = f2tf32(pbt[r] - hf);
                int off = d*72 + ((jb + r) ^ C);
                Bh[off] = hf; Bl[off] = __uint_as_float(lb);
            }
        } else {
#pragma unroll
            for (int r = 0; r < 2; r++) {
                int idx = tid + 256*r, kr = idx >> 4, nq = idx & 15;
                int off = kr*72 + ((nq*4) ^ (((kr >> 2) & 3) << 3));
                float4 v = pb[r];
                float4 h4, l4;
                uint32_t b;
                b = f2tf32(v.x); h4.x = __uint_as_float(b); l4.x = __uint_as_float(f2tf32(v.x - h4.x));
                b = f2tf32(v.y); h4.y = __uint_as_float(b); l4.y = __uint_as_float(f2tf32(v.y - h4.y));
                b = f2tf32(v.z); h4.z = __uint_as_float(b); l4.z = __uint_as_float(f2tf32(v.z - h4.z));
                b = f2tf32(v.w); h4.w = __uint_as_float(b); l4.w = __uint_as_float(f2tf32(v.w - h4.w));
                *(float4*)(Bh + off) = h4;
                *(float4*)(Bl + off) = l4;
            }
        }
    };

    float acc[2][4][4];
#pragma unroll
    for (int a = 0; a < 2; a++)
#pragma unroll
        for (int b = 0; b < 4; b++)
#pragma unroll
            for (int c = 0; c < 4; c++) acc[a][b][c] = 0.f;

    loadA(0); loadB(0);

    for (int kt = 0; kt < NK; kt++) {
        __syncthreads();
        stage();
        __syncthreads();
        int ktn = (kt + 1 < NK) ? kt + 1 : kt;
        loadA(ktn); loadB(ktn);

#pragma unroll
        for (int ks = 0; ks < 4; ks++) {
            uint32_t ah[2][4], al2[2][4], bh[4][2], bl2[4][2];
            const int kA = ks*8 + tig;
            const int C0 = ((kA >> 2) & 3) << 3;           // uniform per warp (tig<4)
            const int C1 = (((kA + 4) >> 2) & 3) << 3;
#pragma unroll
            for (int mt = 0; mt < 2; mt++) {
                int m = wm*32 + mt*16 + gid;
                int mxa = m ^ C0, mya = m ^ C1;
                int i0 = kA*136, i1 = (kA+4)*136;
                ah[mt][0]  = Ahu[i0 + mxa];       ah[mt][1]  = Ahu[i0 + (mxa ^ 8)];
                ah[mt][2]  = Ahu[i1 + mya];       ah[mt][3]  = Ahu[i1 + (mya ^ 8)];
                al2[mt][0] = Alu[i0 + mxa];       al2[mt][1] = Alu[i0 + (mxa ^ 8)];
                al2[mt][2] = Alu[i1 + mya];       al2[mt][3] = Alu[i1 + (mya ^ 8)];
            }
#pragma unroll
            for (int nt = 0; nt < 4; nt++) {
                int n = wn*32 + nt*8 + gid;
                bh[nt][0]  = Bhu[kA*72 + (n ^ C0)];
                bh[nt][1]  = Bhu[(kA+4)*72 + (n ^ C1)];
                bl2[nt][0] = Blu[kA*72 + (n ^ C0)];
                bl2[nt][1] = Blu[(kA+4)*72 + (n ^ C1)];
            }
#pragma unroll
            for (int mt = 0; mt < 2; mt++)
#pragma unroll
                for (int nt = 0; nt < 4; nt++) {
                    mma8(acc[mt][nt], ah[mt],  bh[nt]);
                    mma8(acc[mt][nt], ah[mt],  bl2[nt]);
                    mma8(acc[mt][nt], al2[mt], bh[nt]);
                }
        }
    }

    // epilogue: c0,c1 -> (m, n..n+1); c2,c3 -> (m+8, n..n+1)
#pragma unroll
    for (int mt = 0; mt < 2; mt++) {
        int m = m0 + wm*32 + mt*16 + gid;
#pragma unroll
        for (int nt = 0; nt < 4; nt++) {
            int n = n0 + wn*32 + nt*8 + tig*2;
            float c0 = acc[mt][nt][0], c1 = acc[mt][nt][1];
            float c2 = acc[mt][nt][2], c3 = acc[mt][nt][3];
            if constexpr (MODE==0) {
                float2 bb = *(const float2*)(bias + n);
                int hh = n / 192, rem = n - hh*192, wch = rem >> 6, d = rem & 63;
                float* base = (wch == 0) ? g_Q : (wch == 1) ? g_K : g_V;
                *(float2*)(base + (size_t)(hh*SQ + m)*HD + d)     = make_float2(c0 + bb.x, c1 + bb.y);
                *(float2*)(base + (size_t)(hh*SQ + m + 8)*HD + d) = make_float2(c2 + bb.x, c3 + bb.y);
            } else if constexpr (MODE==1) {
                *(float2*)(g_S + (size_t)(z*SQ + m)*SQ + n)     = make_float2(c0, c1);
                *(float2*)(g_S + (size_t)(z*SQ + m + 8)*SQ + n) = make_float2(c2, c3);
            } else if constexpr (MODE==2) {
                *(float2*)(g_Ctx + (size_t)m*HIDW + z*HD + n)       = make_float2(c0, c1);
                *(float2*)(g_Ctx + (size_t)(m + 8)*HIDW + z*HD + n) = make_float2(c2, c3);
            } else {
                float2 bb = *(const float2*)(bias + n);
                float2 r0 = *(const float2*)(resid + (size_t)m*HIDW + n);
                float2 r1 = *(const float2*)(resid + (size_t)(m + 8)*HIDW + n);
                *(float2*)(outp + (size_t)m*HIDW + n)       = make_float2(c0 + bb.x + r0.x, c1 + bb.y + r0.y);
                *(float2*)(outp + (size_t)(m + 8)*HIDW + n) = make_float2(c2 + bb.x + r1.x, c3 + bb.y + r1.y);
            }
        }
    }
}

// ---------------------------------------------------------------------------
// Per-row softmax: p, A_j = exp(S/64) (masked), P2 = sum p^2.  Block per (h,i).
// ---------------------------------------------------------------------------
__global__ void softmax_k(const float* __restrict__ alibi, const float* __restrict__ mask)
{
    __shared__ float red[8];
    const int row = blockIdx.x;
    const int h = row >> 8, i = row & 255;
    const int j = threadIdx.x;

    float s  = g_S[row*SQ + j];
    float sc = fmaf(0.125f, s, alibi[h*SQ + j]) + mask[i*SQ + j];

    float m = sc;
#pragma unroll
    for (int o = 16; o; o >>= 1) m = fmaxf(m, __shfl_xor_sync(0xffffffffu, m, o));
    if ((j & 31) == 0) red[j >> 5] = m;
    __syncthreads();
    float bm = red[0];
#pragma unroll
    for (int t = 1; t < 8; t++) bm = fmaxf(bm, red[t]);
    float e = ex2f((sc - bm) * LOG2E);
    __syncthreads();

    float su = e;
#pragma unroll
    for (int o = 16; o; o >>= 1) su += __shfl_xor_sync(0xffffffffu, su, o);
    if ((j & 31) == 0) red[j >> 5] = su;
    __syncthreads();
    float tot = red[0];
#pragma unroll
    for (int t = 1; t < 8; t++) tot += red[t];

    float p = e * rcpf(tot);
    g_P[row*SQ + j] = p;
    float a = (j <= i) ? ex2f(s * (LOG2E/64.f)) : 0.f;
    g_AP[row*SQ + j] = make_float2(a, p);

    float pq = p*p;
    __syncthreads();
#pragma unroll
    for (int o = 16; o; o >>= 1) pq += __shfl_xor_sync(0xffffffffu, pq, o);
    if ((j & 31) == 0) red[j >> 5] = pq;
    __syncthreads();
    if (j == 0) {
        float t2 = red[0];
#pragma unroll
        for (int t = 1; t < 8; t++) t2 += red[t];
        g_P2[row] = t2;
    }
}

// ---------------------------------------------------------------------------
// qk_importance: thread = (h, pair(i1, 255-i1), d).  Exactly 257 trips/thread,
// kv load shared between the paired rows; no atomics (per-row partials).
// ---------------------------------------------------------------------------
__global__ void importance_k()
{
    const int tid = threadIdx.x;              // 128 threads
    const int h   = blockIdx.y;
    const int p2  = tid >> 6;
    const int d   = tid & 63;
    const int i1  = blockIdx.x + 64*p2;       // 0..127
    const int i2  = 255 - i1;                 // 128..255
    const int row1 = h*SQ + i1, row2 = h*SQ + i2;

    const float qe1 = g_Q[row1*HD + d] * (-LOG2E/64.f);
    const float qe2 = g_Q[row2*HD + d] * (-LOG2E/64.f);
    const float*  kp  = g_K + h*SQ*HD + d;
    const float2* ap1 = g_AP + (size_t)row1*SQ;
    const float2* ap2 = g_AP + (size_t)row2*SQ;

    float Z1=0.f, W21=0.f, WP1=0.f, Z2=0.f, W22=0.f, WP2=0.f;
    int j = 0;
#pragma unroll 2
    for (; j <= i1; ++j) {
        float kv = kp[j*HD];
        float2 a1 = ap1[j];
        float2 a2 = ap2[j];
        float w1 = a1.x * ex2f(qe1*kv);
        float w2 = a2.x * ex2f(qe2*kv);
        Z1 += w1; W21 = fmaf(w1, w1, W21); WP1 = fmaf(w1, a1.y, WP1);
        Z2 += w2; W22 = fmaf(w2, w2, W22); WP2 = fmaf(w2, a2.y, WP2);
    }
#pragma unroll 4
    for (; j <= i2; ++j) {
        float kv = kp[j*HD];
        float2 a2 = ap2[j];
        float w2 = a2.x * ex2f(qe2*kv);
        Z2 += w2; W22 = fmaf(w2, w2, W22); WP2 = fmaf(w2, a2.y, WP2);
    }
    float iz1 = rcpf(Z1), iz2 = rcpf(Z2);
    g_Part[row1*HD + d] = fmaf(W21*iz1, iz1, -2.f*WP1*iz1) + g_P2[row1];
    g_Part[row2*HD + d] = fmaf(W22*iz2, iz2, -2.f*WP2*iz2) + g_P2[row2];
}

// Two-stage deterministic reduction of g_Part over the 256 rows per head.
__global__ void reduce_part()
{
    const int bx = blockIdx.x;                 // 16 blocks
    const int chunk = bx & 3, og = bx >> 2;
    const int o = og*256 + threadIdx.x;        // h*64+d
    const int h = o >> 6, d = o & 63;
    float s = 0.f;
#pragma unroll 8
    for (int r = 0; r < 64; ++r)
        s += g_Part[(h*SQ + chunk*64 + r)*HD + d];
    g_Part2[chunk*1024 + o] = s;
}

__global__ void reduce_fin(float* __restrict__ imp)
{
    const int o = blockIdx.x*256 + threadIdx.x;
    imp[o] = (g_Part2[o] + g_Part2[1024 + o]) + (g_Part2[2048 + o] + g_Part2[3072 + o]);
}

// ---------------------------------------------------------------------------
extern "C" void kernel_launch(void* const* d_in, const int* in_sizes, int n_in,
                              void* d_out, int out_size)
{
    (void)in_sizes; (void)n_in; (void)out_size;
    const float* hidden   = (const float*)d_in[0];
    const float* residual = (const float*)d_in[1];
    const float* alibi    = (const float*)d_in[2];
    const float* amask    = (const float*)d_in[3];
    const float* Wqkv     = (const float*)d_in[4];
    const float* bqkv     = (const float*)d_in[5];
    const float* Wd       = (const float*)d_in[6];
    const float* bd       = (const float*)d_in[7];
    float* out = (float*)d_out;

    cudaFuncSetAttribute(mma_gemm<0>, cudaFuncAttributeMaxDynamicSharedMemorySize, SMEM_BYTES);
    cudaFuncSetAttribute(mma_gemm<1>, cudaFuncAttributeMaxDynamicSharedMemorySize, SMEM_BYTES);
    cudaFuncSetAttribute(mma_gemm<2>, cudaFuncAttributeMaxDynamicSharedMemorySize, SMEM_BYTES);
    cudaFuncSetAttribute(mma_gemm<3>, cudaFuncAttributeMaxDynamicSharedMemorySize, SMEM_BYTES);

    // QKV projection + Q/K/V scatter
    mma_gemm<0><<<dim3(48,2,1), 256, SMEM_BYTES>>>(hidden, Wqkv, bqkv, nullptr, nullptr);
    // scores S = Q K^T per head
    mma_gemm<1><<<dim3(4,2,16), 256, SMEM_BYTES>>>(nullptr, nullptr, nullptr, nullptr, nullptr);
    // softmax (p, A, P2)
    softmax_k<<<4096, 256>>>(alibi, amask);
    // qk importance + deterministic 2-stage reduce
    importance_k<<<dim3(64,16,1), 128>>>();
    reduce_part<<<16, 256>>>();
    reduce_fin<<<4, 256>>>(out + SQ*HIDW);
    // context = P V per head
    mma_gemm<2><<<dim3(1,2,16), 256, SMEM_BYTES>>>(nullptr, nullptr, nullptr, nullptr, nullptr);
    // dense + bias + residual
    mma_gemm<3><<<dim3(16,2,1), 256, SMEM_BYTES>>>(nullptr, Wd, bd, residual, out);
}

// round 7
// speedup vs baseline: 1.9295x; 1.1912x over previous
#include <cuda_runtime.h>
#include <cstdint>

#define SQ   256
#define NH   16
#define HD   64
#define HIDW 1024
#define LOG2E 1.4426950408889634f

static __device__ float  g_Q[NH*SQ*HD];
static __device__ float  g_K[NH*SQ*HD];
static __device__ float  g_V[NH*SQ*HD];
static __device__ float  g_S[NH*SQ*SQ];
static __device__ float  g_P[NH*SQ*SQ];
static __device__ float2 g_AP[NH*SQ*SQ];
static __device__ float  g_P2[NH*SQ];
static __device__ float  g_Ctx[SQ*HIDW];
static __device__ float  g_Part[NH*SQ*HD];     // [row][d]
static __device__ float  g_Part2[4*NH*HD];     // [chunk][h*64+d]

__device__ __forceinline__ float ex2f(float x){ float y; asm("ex2.approx.ftz.f32 %0, %1;" : "=f"(y) : "f"(x)); return y; }
__device__ __forceinline__ float rcpf(float x){ float y; asm("rcp.approx.ftz.f32 %0, %1;" : "=f"(y) : "f"(x)); return y; }
__device__ __forceinline__ uint32_t f2tf32(float x){ uint32_t r; asm("cvt.rna.tf32.f32 %0, %1;" : "=r"(r) : "f"(x)); return r; }

__device__ __forceinline__ void mma8(float* c, const uint32_t* a, const uint32_t* b){
    asm volatile("mma.sync.aligned.m16n8k8.row.col.f32.tf32.tf32.f32 "
        "{%0,%1,%2,%3}, {%4,%5,%6,%7}, {%8,%9}, {%0,%1,%2,%3};"
        : "+f"(c[0]), "+f"(c[1]), "+f"(c[2]), "+f"(c[3])
        : "r"(a[0]), "r"(a[1]), "r"(a[2]), "r"(a[3]), "r"(b[0]), "r"(b[1]));
}

// ---------------------------------------------------------------------------
// tf32-split GEMM: D[(64*MT) x 64] = A[(64*MT) x KT] * B(k-major)[KT x 64]
// 3-term split (hi*hi + hi*lo + lo*hi) => fp32-grade accuracy on tensor cores.
// MODE 0: fused = hidden @ Wqkv (+bias) -> scatter Q/K/V   [B = Wqkv, direct]
// MODE 1: S[h]  = Q[h] @ K[h]^T                            [B = K, transposed at staging]
// MODE 2: Ctx   = P[h] @ V[h]                              [B = V, direct]
// MODE 3: out   = Ctx @ Wd (+bias+residual)                [B = Wd, direct]
// smem layouts (XOR-swizzled, conflict-free):
//   A: [k][m] stride BM+8, idx = k*(BM+8) + (m ^ (((k>>2)&3)<<3))
//   B: [k][n] stride  72,  idx = k*72    + (n ^ (((k>>2)&3)<<3))
// ---------------------------------------------------------------------------
#define BSZ (32*72)

template<int MODE, int MT>
__global__ void __launch_bounds__(256, 1) mma_gemm(const float* __restrict__ Aext,
                                                   const float* __restrict__ Bext,
                                                   const float* __restrict__ bias,
                                                   const float* __restrict__ resid,
                                                   float* __restrict__ outp)
{
    constexpr int KT  = (MODE==1) ? 64 : (MODE==2) ? 256 : 1024;
    constexpr int NK  = KT/32;
    constexpr int LDA = (MODE==1) ? 64 : (MODE==2) ? 256 : 1024;
    constexpr int LDB = (MODE==0) ? 3072 : (MODE==1) ? 64 : (MODE==2) ? 64 : 1024;
    constexpr int BM  = 64*MT;
    constexpr int AST = BM + 8;
    constexpr int ASZ = 32*AST;

    extern __shared__ float sm[];
    float* Ah = sm;
    float* Al = sm + ASZ;
    float* Bh = sm + 2*ASZ;
    float* Bl = sm + 2*ASZ + BSZ;
    const uint32_t* Ahu = (const uint32_t*)Ah;
    const uint32_t* Alu = (const uint32_t*)Al;
    const uint32_t* Bhu = (const uint32_t*)Bh;
    const uint32_t* Blu = (const uint32_t*)Bl;

    const int tid = threadIdx.x, lane = tid & 31, wid = tid >> 5;
    const int wm = wid >> 1, wn = wid & 1;
    const int tig = lane & 3, gid = lane >> 2;
    const int n0 = blockIdx.x*64, m0 = blockIdx.y*BM, z = blockIdx.z;

    const float* Ag; const float* Bg;
    if constexpr (MODE==0)      { Ag = Aext;                      Bg = Bext; }
    else if constexpr (MODE==1) { Ag = g_Q + z*SQ*HD;             Bg = g_K + z*SQ*HD; }
    else if constexpr (MODE==2) { Ag = g_P + (size_t)z*SQ*SQ;     Bg = g_V + z*SQ*HD; }
    else                        { Ag = g_Ctx;                     Bg = Bext; }

    // staging maps
    const int kqw = tid & 3, mrw = (tid >> 2) & 7, aw = tid >> 5;   // A
    float4 pa[2*MT]; float4 pb[2]; float pbt[8];

    auto loadA = [&](int kt){
#pragma unroll
        for (int mi = 0; mi < MT; mi++)
#pragma unroll
            for (int ki = 0; ki < 2; ki++) {
                int m = aw*8 + mrw + 64*mi, kq = kqw + 4*ki;
                pa[mi*2+ki] = *(const float4*)(Ag + (size_t)(m0+m)*LDA + kt*32 + kq*4);
            }
    };
    auto loadB = [&](int kt){
        if constexpr (MODE==1) {
            int d = tid & 31, jb = (tid >> 5) * 8;
#pragma unroll
            for (int r = 0; r < 8; r++)
                pbt[r] = Bg[(size_t)(n0 + jb + r)*LDB + kt*32 + d];
        } else {
#pragma unroll
            for (int r = 0; r < 2; r++) {
                int idx = tid + 256*r, kr = idx >> 4, nq = idx & 15;
                pb[r] = *(const float4*)(Bg + (size_t)(kt*32 + kr)*LDB + n0 + nq*4);
            }
        }
    };
    auto stage = [&](){
#pragma unroll
        for (int mi = 0; mi < MT; mi++)
#pragma unroll
            for (int ki = 0; ki < 2; ki++) {
                int m = aw*8 + mrw + 64*mi, kq = kqw + 4*ki;
                int mb = m ^ ((kq & 3) << 3);
                float4 v = pa[mi*2+ki];
                float vv[4] = {v.x, v.y, v.z, v.w};
#pragma unroll
                for (int e = 0; e < 4; e++) {
                    uint32_t hb = f2tf32(vv[e]);
                    float hf = __uint_as_float(hb);
                    uint32_t lb = f2tf32(vv[e] - hf);
                    Ah[(kq*4+e)*AST + mb] = hf;
                    Al[(kq*4+e)*AST + mb] = __uint_as_float(lb);
                }
            }
        if constexpr (MODE==1) {
            int d = tid & 31, jb = (tid >> 5) * 8;
            int C = ((d >> 2) & 3) << 3;
#pragma unroll
            for (int r = 0; r < 8; r++) {
                uint32_t hb = f2tf32(pbt[r]);
                float hf = __uint_as_float(hb);
                uint32_t lb = f2tf32(pbt[r] - hf);
                int off = d*72 + ((jb + r) ^ C);
                Bh[off] = hf; Bl[off] = __uint_as_float(lb);
            }
        } else {
#pragma unroll
            for (int r = 0; r < 2; r++) {
                int idx = tid + 256*r, kr = idx >> 4, nq = idx & 15;
                int off = kr*72 + ((nq*4) ^ (((kr >> 2) & 3) << 3));
                float4 v = pb[r];
                float4 h4, l4;
                uint32_t b;
                b = f2tf32(v.x); h4.x = __uint_as_float(b); l4.x = __uint_as_float(f2tf32(v.x - h4.x));
                b = f2tf32(v.y); h4.y = __uint_as_float(b); l4.y = __uint_as_float(f2tf32(v.y - h4.y));
                b = f2tf32(v.z); h4.z = __uint_as_float(b); l4.z = __uint_as_float(f2tf32(v.z - h4.z));
                b = f2tf32(v.w); h4.w = __uint_as_float(b); l4.w = __uint_as_float(f2tf32(v.w - h4.w));
                *(float4*)(Bh + off) = h4;
                *(float4*)(Bl + off) = l4;
            }
        }
    };

    float acc[MT][4][4];
#pragma unroll
    for (int a = 0; a < MT; a++)
#pragma unroll
        for (int b = 0; b < 4; b++)
#pragma unroll
            for (int c = 0; c < 4; c++) acc[a][b][c] = 0.f;

    loadA(0); loadB(0);

    for (int kt = 0; kt < NK; kt++) {
        __syncthreads();
        stage();
        __syncthreads();
        int ktn = (kt + 1 < NK) ? kt + 1 : kt;
        loadA(ktn); loadB(ktn);

#pragma unroll
        for (int ks = 0; ks < 4; ks++) {
            uint32_t ah[MT][4], al2[MT][4], bh[4][2], bl2[4][2];
            const int kA = ks*8 + tig;
            const int C0 = ((kA >> 2) & 3) << 3;           // uniform per warp (tig<4)
            const int C1 = (((kA + 4) >> 2) & 3) << 3;
#pragma unroll
            for (int mt = 0; mt < MT; mt++) {
                int m = wm*(16*MT) + mt*16 + gid;
                int mxa = m ^ C0, mya = m ^ C1;
                int i0 = kA*AST, i1 = (kA+4)*AST;
                ah[mt][0]  = Ahu[i0 + mxa];       ah[mt][1]  = Ahu[i0 + (mxa ^ 8)];
                ah[mt][2]  = Ahu[i1 + mya];       ah[mt][3]  = Ahu[i1 + (mya ^ 8)];
                al2[mt][0] = Alu[i0 + mxa];       al2[mt][1] = Alu[i0 + (mxa ^ 8)];
                al2[mt][2] = Alu[i1 + mya];       al2[mt][3] = Alu[i1 + (mya ^ 8)];
            }
#pragma unroll
            for (int nt = 0; nt < 4; nt++) {
                int n = wn*32 + nt*8 + gid;
                bh[nt][0]  = Bhu[kA*72 + (n ^ C0)];
                bh[nt][1]  = Bhu[(kA+4)*72 + (n ^ C1)];
                bl2[nt][0] = Blu[kA*72 + (n ^ C0)];
                bl2[nt][1] = Blu[(kA+4)*72 + (n ^ C1)];
            }
#pragma unroll
            for (int mt = 0; mt < MT; mt++)
#pragma unroll
                for (int nt = 0; nt < 4; nt++) {
                    mma8(acc[mt][nt], ah[mt],  bh[nt]);
                    mma8(acc[mt][nt], ah[mt],  bl2[nt]);
                    mma8(acc[mt][nt], al2[mt], bh[nt]);
                }
        }
    }

    // epilogue: c0,c1 -> (m, n..n+1); c2,c3 -> (m+8, n..n+1)
#pragma unroll
    for (int mt = 0; mt < MT; mt++) {
        int m = m0 + wm*(16*MT) + mt*16 + gid;
#pragma unroll
        for (int nt = 0; nt < 4; nt++) {
            int n = n0 + wn*32 + nt*8 + tig*2;
            float c0 = acc[mt][nt][0], c1 = acc[mt][nt][1];
            float c2 = acc[mt][nt][2], c3 = acc[mt][nt][3];
            if constexpr (MODE==0) {
                float2 bb = *(const float2*)(bias + n);
                int hh = n / 192, rem = n - hh*192, wch = rem >> 6, d = rem & 63;
                float* base = (wch == 0) ? g_Q : (wch == 1) ? g_K : g_V;
                *(float2*)(base + (size_t)(hh*SQ + m)*HD + d)     = make_float2(c0 + bb.x, c1 + bb.y);
                *(float2*)(base + (size_t)(hh*SQ + m + 8)*HD + d) = make_float2(c2 + bb.x, c3 + bb.y);
            } else if constexpr (MODE==1) {
                *(float2*)(g_S + (size_t)(z*SQ + m)*SQ + n)     = make_float2(c0, c1);
                *(float2*)(g_S + (size_t)(z*SQ + m + 8)*SQ + n) = make_float2(c2, c3);
            } else if constexpr (MODE==2) {
                *(float2*)(g_Ctx + (size_t)m*HIDW + z*HD + n)       = make_float2(c0, c1);
                *(float2*)(g_Ctx + (size_t)(m + 8)*HIDW + z*HD + n) = make_float2(c2, c3);
            } else {
                float2 bb = *(const float2*)(bias + n);
                float2 r0 = *(const float2*)(resid + (size_t)m*HIDW + n);
                float2 r1 = *(const float2*)(resid + (size_t)(m + 8)*HIDW + n);
                *(float2*)(outp + (size_t)m*HIDW + n)       = make_float2(c0 + bb.x + r0.x, c1 + bb.y + r0.y);
                *(float2*)(outp + (size_t)(m + 8)*HIDW + n) = make_float2(c2 + bb.x + r1.x, c3 + bb.y + r1.y);
            }
        }
    }
}

// ---------------------------------------------------------------------------
// Per-row softmax: p, A_j = exp(S/64) (masked), P2 = sum p^2.  Block per (h,i).
// ---------------------------------------------------------------------------
__global__ void softmax_k(const float* __restrict__ alibi, const float* __restrict__ mask)
{
    __shared__ float red[8];
    const int row = blockIdx.x;
    const int h = row >> 8, i = row & 255;
    const int j = threadIdx.x;

    float s  = g_S[row*SQ + j];
    float sc = fmaf(0.125f, s, alibi[h*SQ + j]) + mask[i*SQ + j];

    float m = sc;
#pragma unroll
    for (int o = 16; o; o >>= 1) m = fmaxf(m, __shfl_xor_sync(0xffffffffu, m, o));
    if ((j & 31) == 0) red[j >> 5] = m;
    __syncthreads();
    float bm = red[0];
#pragma unroll
    for (int t = 1; t < 8; t++) bm = fmaxf(bm, red[t]);
    float e = ex2f((sc - bm) * LOG2E);
    __syncthreads();

    float su = e;
#pragma unroll
    for (int o = 16; o; o >>= 1) su += __shfl_xor_sync(0xffffffffu, su, o);
    if ((j & 31) == 0) red[j >> 5] = su;
    __syncthreads();
    float tot = red[0];
#pragma unroll
    for (int t = 1; t < 8; t++) tot += red[t];

    float p = e * rcpf(tot);
    g_P[row*SQ + j] = p;
    float a = (j <= i) ? ex2f(s * (LOG2E/64.f)) : 0.f;
    g_AP[row*SQ + j] = make_float2(a, p);

    float pq = p*p;
    __syncthreads();
#pragma unroll
    for (int o = 16; o; o >>= 1) pq += __shfl_xor_sync(0xffffffffu, pq, o);
    if ((j & 31) == 0) red[j >> 5] = pq;
    __syncthreads();
    if (j == 0) {
        float t2 = red[0];
#pragma unroll
        for (int t = 1; t < 8; t++) t2 += red[t];
        g_P2[row] = t2;
    }
}

// ---------------------------------------------------------------------------
// qk_importance: thread = (h, pair(i1, 255-i1), d).  Unroll-4 with batched
// loads; loop bounds rounded up to x4 exploiting g_AP[.].x == 0 for masked j
// (zero contribution => no causality branches, no double counting).
// Phase 1 covers j in [0, e1) for BOTH rows; phase 2 [e1, e2) for row2 only.
// ---------------------------------------------------------------------------
__global__ void importance_k()
{
    const int tid = threadIdx.x;              // 128 threads
    const int h   = blockIdx.y;
    const int p2  = tid >> 6;
    const int d   = tid & 63;
    const int i1  = blockIdx.x + 64*p2;       // 0..127
    const int i2  = 255 - i1;                 // 128..255
    const int row1 = h*SQ + i1, row2 = h*SQ + i2;

    const float qe1 = g_Q[row1*HD + d] * (-LOG2E/64.f);
    const float qe2 = g_Q[row2*HD + d] * (-LOG2E/64.f);
    const float*  kp  = g_K + h*SQ*HD + d;
    const float4* ap1 = (const float4*)(g_AP + (size_t)row1*SQ);
    const float4* ap2 = (const float4*)(g_AP + (size_t)row2*SQ);

    float Z1=0.f, W21=0.f, WP1=0.f, Z2=0.f, W22=0.f, WP2=0.f;
    const int e1 = (i1 + 4) & ~3;             // multiple of 4, >= i1+1, <= 128
    const int e2 = (i2 + 4) & ~3;             // multiple of 4, >= i2+1, <= 256
    int j = 0;
    for (; j < e1; j += 4) {
        float k0 = kp[(j+0)*HD], k1 = kp[(j+1)*HD];
        float k2 = kp[(j+2)*HD], k3 = kp[(j+3)*HD];
        float4 u0 = ap1[(j>>1)], u1 = ap1[(j>>1)+1];
        float4 v0 = ap2[(j>>1)], v1 = ap2[(j>>1)+1];
        float e0 = ex2f(qe1*k0), e1x = ex2f(qe1*k1), e2x = ex2f(qe1*k2), e3 = ex2f(qe1*k3);
        float f0 = ex2f(qe2*k0), f1 = ex2f(qe2*k1), f2 = ex2f(qe2*k2), f3 = ex2f(qe2*k3);
        float w;
        w = u0.x*e0;  Z1 += w; W21 = fmaf(w,w,W21); WP1 = fmaf(w,u0.y,WP1);
        w = u0.z*e1x; Z1 += w; W21 = fmaf(w,w,W21); WP1 = fmaf(w,u0.w,WP1);
        w = u1.x*e2x; Z1 += w; W21 = fmaf(w,w,W21); WP1 = fmaf(w,u1.y,WP1);
        w = u1.z*e3;  Z1 += w; W21 = fmaf(w,w,W21); WP1 = fmaf(w,u1.w,WP1);
        w = v0.x*f0;  Z2 += w; W22 = fmaf(w,w,W22); WP2 = fmaf(w,v0.y,WP2);
        w = v0.z*f1;  Z2 += w; W22 = fmaf(w,w,W22); WP2 = fmaf(w,v0.w,WP2);
        w = v1.x*f2;  Z2 += w; W22 = fmaf(w,w,W22); WP2 = fmaf(w,v1.y,WP2);
        w = v1.z*f3;  Z2 += w; W22 = fmaf(w,w,W22); WP2 = fmaf(w,v1.w,WP2);
    }
    for (; j < e2; j += 4) {
        float k0 = kp[(j+0)*HD], k1 = kp[(j+1)*HD];
        float k2 = kp[(j+2)*HD], k3 = kp[(j+3)*HD];
        float4 v0 = ap2[(j>>1)], v1 = ap2[(j>>1)+1];
        float f0 = ex2f(qe2*k0), f1 = ex2f(qe2*k1), f2 = ex2f(qe2*k2), f3 = ex2f(qe2*k3);
        float w;
        w = v0.x*f0; Z2 += w; W22 = fmaf(w,w,W22); WP2 = fmaf(w,v0.y,WP2);
        w = v0.z*f1; Z2 += w; W22 = fmaf(w,w,W22); WP2 = fmaf(w,v0.w,WP2);
        w = v1.x*f2; Z2 += w; W22 = fmaf(w,w,W22); WP2 = fmaf(w,v1.y,WP2);
        w = v1.z*f3; Z2 += w; W22 = fmaf(w,w,W22); WP2 = fmaf(w,v1.w,WP2);
    }
    float iz1 = rcpf(Z1), iz2 = rcpf(Z2);
    g_Part[row1*HD + d] = fmaf(W21*iz1, iz1, -2.f*WP1*iz1) + g_P2[row1];
    g_Part[row2*HD + d] = fmaf(W22*iz2, iz2, -2.f*WP2*iz2) + g_P2[row2];
}

// Two-stage deterministic reduction of g_Part over the 256 rows per head.
__global__ void reduce_part()
{
    const int bx = blockIdx.x;                 // 16 blocks
    const int chunk = bx & 3, og = bx >> 2;
    const int o = og*256 + threadIdx.x;        // h*64+d
    const int h = o >> 6, d = o & 63;
    float s = 0.f;
#pragma unroll 8
    for (int r = 0; r < 64; ++r)
        s += g_Part[(h*SQ + chunk*64 + r)*HD + d];
    g_Part2[chunk*1024 + o] = s;
}

__global__ void reduce_fin(float* __restrict__ imp)
{
    const int o = blockIdx.x*256 + threadIdx.x;
    imp[o] = (g_Part2[o] + g_Part2[1024 + o]) + (g_Part2[2048 + o] + g_Part2[3072 + o]);
}

// ---------------------------------------------------------------------------
extern "C" void kernel_launch(void* const* d_in, const int* in_sizes, int n_in,
                              void* d_out, int out_size)
{
    (void)in_sizes; (void)n_in; (void)out_size;
    const float* hidden   = (const float*)d_in[0];
    const float* residual = (const float*)d_in[1];
    const float* alibi    = (const float*)d_in[2];
    const float* amask    = (const float*)d_in[3];
    const float* Wqkv     = (const float*)d_in[4];
    const float* bqkv     = (const float*)d_in[5];
    const float* Wd       = (const float*)d_in[6];
    const float* bd       = (const float*)d_in[7];
    float* out = (float*)d_out;

    constexpr int SMEM2 = (2*32*136 + 2*BSZ)*4;   // MT=2: 53248
    constexpr int SMEM1 = (2*32*72  + 2*BSZ)*4;   // MT=1: 36864

    cudaFuncSetAttribute(mma_gemm<0,2>, cudaFuncAttributeMaxDynamicSharedMemorySize, SMEM2);
    cudaFuncSetAttribute(mma_gemm<1,2>, cudaFuncAttributeMaxDynamicSharedMemorySize, SMEM2);
    cudaFuncSetAttribute(mma_gemm<2,1>, cudaFuncAttributeMaxDynamicSharedMemorySize, SMEM1);
    cudaFuncSetAttribute(mma_gemm<3,1>, cudaFuncAttributeMaxDynamicSharedMemorySize, SMEM1);

    // QKV projection + Q/K/V scatter (96 blocks)
    mma_gemm<0,2><<<dim3(48,2,1), 256, SMEM2>>>(hidden, Wqkv, bqkv, nullptr, nullptr);
    // scores S = Q K^T per head (128 blocks)
    mma_gemm<1,2><<<dim3(4,2,16), 256, SMEM2>>>(nullptr, nullptr, nullptr, nullptr, nullptr);
    // softmax (p, A, P2)
    softmax_k<<<4096, 256>>>(alibi, amask);
    // qk importance + deterministic 2-stage reduce
    importance_k<<<dim3(64,16,1), 128>>>();
    reduce_part<<<16, 256>>>();
    reduce_fin<<<4, 256>>>(out + SQ*HIDW);
    // context = P V per head (64 blocks, BM=64)
    mma_gemm<2,1><<<dim3(1,4,16), 256, SMEM1>>>(nullptr, nullptr, nullptr, nullptr, nullptr);
    // dense + bias + residual (64 blocks, BM=64)
    mma_gemm<3,1><<<dim3(16,4,1), 256, SMEM1>>>(nullptr, Wd, bd, residual, out);
}